// round 17
// baseline (speedup 1.0000x reference)
#include <cuda_runtime.h>
#include <cuda_fp16.h>
#include <math.h>
#include <stdint.h>

// Problem constants
#define TDIM 4096          // B*S tokens
#define HDIM 1024          // hidden
#define EDIM 8             // experts
#define FDIM 2048          // ffn
#define KSEL 2             // top-k
#define NROWS (TDIM*KSEL)  // 8192 dispatch rows
#define GEMM_GRID 296      // 2 CTAs/SM x 148 SMs

// ==================== device scratch (allocation-free) ====================
__device__ __half g_xh[(size_t)TDIM * HDIM];              // x fp16 [T][H]
__device__ __half g_w1h[(size_t)EDIM * HDIM * 2 * FDIM];  // w_in  fp16 [E][H][2F]
__device__ __half g_w2h[(size_t)EDIM * FDIM * HDIM];      // w_out fp16 [E][F][H]
__device__ __half g_glu[(size_t)NROWS * FDIM];            // GLU acts fp16 (list order)
__device__ float  g_pairs[(size_t)NROWS * HDIM];          // expert outputs per (token,slot)
__device__ int   g_eid[NROWS];
__device__ float g_gate[NROWS];
__device__ int   g_list[NROWS];
__device__ int   g_freq[EDIM];
__device__ int   g_cursor[EDIM];
__device__ int   g_offsets[EDIM + 1];
__device__ int   g_w1off[EDIM + 1];   // gemm1 work-item prefix (last = total)
__device__ int   g_w2off[EDIM + 1];   // gemm2 work-item prefix (last = total)
__device__ float g_psum[EDIM];
__device__ float g_lsesq;

// ==================== PTX helpers (sm_80-baseline features only) ====================
__device__ __forceinline__ uint32_t smem_u32(const void* p) {
    uint32_t a;
    asm("{ .reg .u64 t; cvta.to.shared.u64 t, %1; cvt.u32.u64 %0, t; }" : "=r"(a) : "l"(p));
    return a;
}
__device__ __forceinline__ void cp16(uint32_t dst, const void* src) {
    asm volatile("cp.async.cg.shared.global [%0], [%1], 16;" :: "r"(dst), "l"(src));
}
#define CP_COMMIT() asm volatile("cp.async.commit_group;" ::: "memory")
#define CP_WAIT1()  asm volatile("cp.async.wait_group 1;" ::: "memory")
#define CP_WAIT0()  asm volatile("cp.async.wait_group 0;" ::: "memory")

__device__ __forceinline__ void ldsm4(uint32_t& r0, uint32_t& r1, uint32_t& r2, uint32_t& r3,
                                      uint32_t a) {
    asm volatile("ldmatrix.sync.aligned.m8n8.x4.shared.b16 {%0,%1,%2,%3}, [%4];"
                 : "=r"(r0), "=r"(r1), "=r"(r2), "=r"(r3) : "r"(a));
}
__device__ __forceinline__ void ldsm4t(uint32_t& r0, uint32_t& r1, uint32_t& r2, uint32_t& r3,
                                       uint32_t a) {
    asm volatile("ldmatrix.sync.aligned.m8n8.x4.trans.shared.b16 {%0,%1,%2,%3}, [%4];"
                 : "=r"(r0), "=r"(r1), "=r"(r2), "=r"(r3) : "r"(a));
}
// fp16 MMA: D(16x8,f32) += A(16x16,f16) * B(16x8,f16)  [row.col]
__device__ __forceinline__ void mma_f16(float* d, const uint32_t* a, const uint32_t* b) {
    asm volatile(
        "mma.sync.aligned.m16n8k16.row.col.f32.f16.f16.f32 "
        "{%0,%1,%2,%3}, {%4,%5,%6,%7}, {%8,%9}, {%0,%1,%2,%3};"
        : "+f"(d[0]), "+f"(d[1]), "+f"(d[2]), "+f"(d[3])
        : "r"(a[0]), "r"(a[1]), "r"(a[2]), "r"(a[3]), "r"(b[0]), "r"(b[1]));
}

// ---- Shared-memory tile geometry ----
#define AROWB 80                             // A row stride bytes (banks 20r%32 distinct)
#define BROWB 272                            // B row stride bytes (banks 4r distinct)
#define A_STG_B (128*AROWB)                  // 10240 B
#define B_STG_B (32*BROWB)                   // 8704 B
#define SM_AS 512                            // after s_tok[128]
#define SM_BS (SM_AS + 2*A_STG_B)            // 20992
#define GEMM_SMEM (SM_BS + 2*B_STG_B)        // 38400

// ==================== reset counters (graph replays) ====================
__global__ void zero_kernel() {
    int i = threadIdx.x;
    if (i < EDIM) { g_freq[i] = 0; g_cursor[i] = 0; g_psum[i] = 0.f; }
    if (i == 0) g_lsesq = 0.f;
}

// ==================== fp16 streaming conversion ====================
__global__ void convh_kernel(const float4* __restrict__ src, uint2* __restrict__ dst, int n4) {
    int i = blockIdx.x * 256 + threadIdx.x;
    if (i < n4) {
        float4 v = src[i];
        __half2 h01 = __floats2half2_rn(v.x, v.y);
        __half2 h23 = __floats2half2_rn(v.z, v.w);
        uint2 o;
        o.x = *(uint32_t*)&h01;
        o.y = *(uint32_t*)&h23;
        dst[i] = o;
    }
}

// ==================== router (vectorized; emits x as fp16; block-aggregated stats) ====================
__global__ void router_kernel(const float* __restrict__ x,
                              const float* __restrict__ wr) {
    __shared__ float s_probs[8][EDIM];   // per-warp softmax probs
    __shared__ float s_lse[8];           // per-warp lse
    __shared__ int   s_top[8][2];        // per-warp top-2 ids
    int tid = threadIdx.x;
    int wrp = tid >> 5;
    int lane = tid & 31;
    int t = blockIdx.x * 8 + wrp;

    float acc[8] = {0.f,0.f,0.f,0.f,0.f,0.f,0.f,0.f};
    const float4* xp4 = (const float4*)(x + (size_t)t * HDIM);
    __half2* xh2 = (__half2*)(g_xh + (size_t)t * HDIM);

    for (int i = lane; i < HDIM / 4; i += 32) {
        float4 xv = xp4[i];
        xh2[2 * i]     = __floats2half2_rn(xv.x, xv.y);
        xh2[2 * i + 1] = __floats2half2_rn(xv.z, xv.w);
        const float xs[4] = {xv.x, xv.y, xv.z, xv.w};
        const int h = i * 4;
#pragma unroll
        for (int j = 0; j < 4; j++) {
            float4 w0 = *(const float4*)(wr + (size_t)(h + j) * 8);
            float4 w1 = *(const float4*)(wr + (size_t)(h + j) * 8 + 4);
            acc[0] += xs[j] * w0.x; acc[1] += xs[j] * w0.y;
            acc[2] += xs[j] * w0.z; acc[3] += xs[j] * w0.w;
            acc[4] += xs[j] * w1.x; acc[5] += xs[j] * w1.y;
            acc[6] += xs[j] * w1.z; acc[7] += xs[j] * w1.w;
        }
    }
#pragma unroll
    for (int e = 0; e < 8; e++)
#pragma unroll
        for (int o = 16; o > 0; o >>= 1)
            acc[e] += __shfl_down_sync(0xffffffffu, acc[e], o);

    if (lane == 0) {
        float m = acc[0];
#pragma unroll
        for (int e = 1; e < 8; e++) m = fmaxf(m, acc[e]);
        float ex[8], sum = 0.f;
#pragma unroll
        for (int e = 0; e < 8; e++) { ex[e] = expf(acc[e] - m); sum += ex[e]; }
        float inv = 1.f / sum;
        float lse = m + logf(sum);

        int i0 = 0;
#pragma unroll
        for (int e = 1; e < 8; e++) if (acc[e] > acc[i0]) i0 = e;
        int i1 = (i0 == 0) ? 1 : 0;
#pragma unroll
        for (int e = 0; e < 8; e++) if (e != i0 && acc[e] > acc[i1]) i1 = e;

        float d = expf(acc[i1] - acc[i0]);
        float g0 = 1.f / (1.f + d);
        float g1 = d / (1.f + d);

        g_eid[2 * t]     = i0;  g_eid[2 * t + 1]  = i1;
        g_gate[2 * t]    = g0;  g_gate[2 * t + 1] = g1;
#pragma unroll
        for (int e = 0; e < 8; e++) s_probs[wrp][e] = ex[e] * inv;
        s_lse[wrp] = lse;
        s_top[wrp][0] = i0;
        s_top[wrp][1] = i1;
    }
    __syncthreads();

    // block aggregation: 8 threads each own one expert
    if (tid < EDIM) {
        float ps = 0.f;
        int fc = 0;
#pragma unroll
        for (int w = 0; w < 8; w++) {
            ps += s_probs[w][tid];
            fc += (s_top[w][0] == tid) + (s_top[w][1] == tid);
        }
        atomicAdd(&g_psum[tid], ps);
        if (fc) atomicAdd(&g_freq[tid], fc);
    }
    if (tid == 8) {
        float ls = 0.f;
#pragma unroll
        for (int w = 0; w < 8; w++) ls += s_lse[w] * s_lse[w];
        atomicAdd(&g_lsesq, ls);
    }
}

// scan: token offsets + persistent-GEMM work-item tables
__global__ void scan_kernel() {
    if (threadIdx.x == 0) {
        int s = 0, s1 = 0, s2 = 0;
        for (int e = 0; e < EDIM; e++) {
            g_offsets[e] = s;
            g_w1off[e] = s1;
            g_w2off[e] = s2;
            int c = g_freq[e];
            int rt = (c + 127) >> 7;
            s += c;
            s1 += rt * (FDIM / 64);     // 32 n-tiles per row tile
            s2 += rt * (HDIM / 128);    // 8 n-tiles per row tile
        }
        g_offsets[EDIM] = s;
        g_w1off[EDIM] = s1;
        g_w2off[EDIM] = s2;
    }
}

// scatter with two-phase smem aggregation (1 global RMW per expert per block)
__global__ void scatter_kernel() {
    __shared__ int s_cnt[EDIM];
    __shared__ int s_base[EDIM];
    int tid = threadIdx.x;
    if (tid < EDIM) s_cnt[tid] = 0;
    __syncthreads();

    int r = blockIdx.x * blockDim.x + tid;
    int e = g_eid[r];
    int lrank = atomicAdd(&s_cnt[e], 1);
    __syncthreads();
    if (tid < EDIM) s_base[tid] = atomicAdd(&g_cursor[tid], s_cnt[tid]);
    __syncthreads();
    g_list[g_offsets[e] + s_base[e] + lrank] = r;
}

// ==================== tile loaders (128 threads, fp16, k-major B) ====================
__device__ __forceinline__ void g1_load(const __half* __restrict__ w1,
                                        const int* s_tok,
                                        uint32_t as_u, uint32_t bs_u,
                                        int tid, int n0, int c, int st) {
    const int k0 = c * 32;
#pragma unroll
    for (int i = 0; i < 4; i++) {
        int idx = tid + i * 128;
        int row = idx >> 2, seg = idx & 3;
        const __half* src = g_xh + (size_t)s_tok[row] * HDIM + k0 + seg * 8;
        cp16(as_u + (uint32_t)(st * A_STG_B + row * AROWB + seg * 16), src);
    }
#pragma unroll
    for (int i = 0; i < 4; i++) {
        int idx = tid + i * 128;
        int kr = idx >> 4, j16 = idx & 15;
        int grp = j16 >> 2, cloc = (j16 & 3) * 8;
        int col = ((grp & 1) ? FDIM : 0) + n0 + (grp >> 1) * 32 + cloc;
        const __half* src = w1 + (size_t)(k0 + kr) * (2 * FDIM) + col;
        cp16(bs_u + (uint32_t)(st * B_STG_B + kr * BROWB + j16 * 16), src);
    }
    CP_COMMIT();
}

__device__ __forceinline__ void g2_load(const __half* __restrict__ w2,
                                        int off, int row0, int rlim,
                                        uint32_t as_u, uint32_t bs_u,
                                        int tid, int n1, int c, int st) {
    const int k0 = c * 32;
#pragma unroll
    for (int i = 0; i < 4; i++) {
        int idx = tid + i * 128;
        int row = idx >> 2, seg = idx & 3;
        int rr = (row < rlim) ? row : (rlim - 1);
        const __half* src = g_glu + (size_t)(off + row0 + rr) * FDIM + k0 + seg * 8;
        cp16(as_u + (uint32_t)(st * A_STG_B + row * AROWB + seg * 16), src);
    }
#pragma unroll
    for (int i = 0; i < 4; i++) {
        int idx = tid + i * 128;
        int kr = idx >> 4, j16 = idx & 15;
        const __half* src = w2 + (size_t)(k0 + kr) * HDIM + n1 + j16 * 8;
        cp16(bs_u + (uint32_t)(st * B_STG_B + kr * BROWB + j16 * 16), src);
    }
    CP_COMMIT();
}

// one K=32 chunk via ldmatrix
__device__ __forceinline__ void chunk_mma(uint32_t a_st, uint32_t b_st,
                                          int wm, int wn, int lane,
                                          float acc[4][8][4]) {
    const int l15 = lane & 15, l16 = lane >> 4;
#pragma unroll
    for (int ks = 0; ks < 2; ks++) {
        uint32_t af[4][4];
#pragma unroll
        for (int i = 0; i < 4; i++) {
            uint32_t addr = a_st + (uint32_t)((wm * 64 + i * 16 + l15) * AROWB + l16 * 16 + ks * 32);
            ldsm4(af[i][0], af[i][1], af[i][2], af[i][3], addr);
        }
        uint32_t bf[8][2];
#pragma unroll
        for (int fg = 0; fg < 4; fg++) {
            uint32_t addr = b_st + (uint32_t)((ks * 16 + l15) * BROWB + (wn * 64 + fg * 16 + l16 * 8) * 2);
            uint32_t r0, r1, r2, r3;
            ldsm4t(r0, r1, r2, r3, addr);
            bf[fg * 2][0] = r0;     bf[fg * 2][1] = r1;
            bf[fg * 2 + 1][0] = r2; bf[fg * 2 + 1][1] = r3;
        }
#pragma unroll
        for (int i = 0; i < 4; i++)
#pragma unroll
            for (int f = 0; f < 8; f++)
                mma_f16(acc[i][f], af[i], bf[f]);
    }
}

// ==================== GEMM1 (persistent): x[tok] @ w_in[e], fused GLU ====================
__global__ void __launch_bounds__(128) gemm1_mma(const __half* __restrict__ w1e) {
    extern __shared__ char smem[];
    int* s_tok = (int*)smem;
    const uint32_t su = smem_u32(smem);
    const uint32_t as_u = su + SM_AS, bs_u = su + SM_BS;

    const int tid = threadIdx.x;
    const int lane = tid & 31, wid = tid >> 5;
    const int wm = wid & 1, wn = wid >> 1;
    const int g = lane >> 2, tq = lane & 3;

    int woff[EDIM + 1];
#pragma unroll
    for (int k = 0; k <= EDIM; k++) woff[k] = g_w1off[k];
    const int tot = woff[EDIM];

    for (int w = blockIdx.x; w < tot; w += (int)gridDim.x) {
        int e = 0;
#pragma unroll
        for (int k = 1; k < EDIM; k++) e = (w >= woff[k]) ? k : e;
        const int local = w - woff[e];
        const int row0 = (local >> 5) * 128;
        const int n0 = (local & 31) << 6;
        const int cnt = g_freq[e];
        const int off = g_offsets[e];

        __syncthreads();
        {
            int r = row0 + tid;
            s_tok[tid] = g_list[off + ((r < cnt) ? r : (cnt - 1))] >> 1;
        }
        __syncthreads();

        const __half* w1 = w1e + (size_t)e * HDIM * (2 * FDIM);

        float acc[4][8][4];
#pragma unroll
        for (int i = 0; i < 4; i++)
#pragma unroll
            for (int f = 0; f < 8; f++)
#pragma unroll
                for (int q = 0; q < 4; q++) acc[i][f][q] = 0.f;

        const int NCH = HDIM / 32;  // 32
        g1_load(w1, s_tok, as_u, bs_u, tid, n0, 0, 0);
        g1_load(w1, s_tok, as_u, bs_u, tid, n0, 1, 1);
        CP_WAIT1();
        __syncthreads();

        for (int c = 0; c < NCH; c++) {
            const int st = c & 1;
            chunk_mma(as_u + st * A_STG_B, bs_u + st * B_STG_B, wm, wn, lane, acc);
            __syncthreads();
            if (c + 2 < NCH) g1_load(w1, s_tok, as_u, bs_u, tid, n0, c + 2, st);
            if (c + 1 < NCH) {
                if (c + 2 < NCH) CP_WAIT1(); else CP_WAIT0();
                __syncthreads();
            }
        }

        // epilogue: GLU -> fp16 g_glu
#pragma unroll
        for (int i = 0; i < 4; i++) {
            const int rbase = wm * 64 + i * 16 + g;
#pragma unroll
            for (int hr = 0; hr < 2; hr++) {
                const int r = rbase + hr * 8;
                if (row0 + r < cnt) {
                    __half2* dst = (__half2*)(g_glu + (size_t)(off + row0 + r) * FDIM + n0 + wn * 32);
#pragma unroll
                    for (int f = 0; f < 4; f++) {
                        float a0 = acc[i][f][hr * 2], a1 = acc[i][f][hr * 2 + 1];
                        float v0 = acc[i][f + 4][hr * 2], v1 = acc[i][f + 4][hr * 2 + 1];
                        float o0 = (a0 / (1.f + __expf(-a0))) * v0;
                        float o1 = (a1 / (1.f + __expf(-a1))) * v1;
                        dst[f * 4 + tq] = __floats2half2_rn(o0, o1);
                    }
                }
            }
        }
    }
}

// ==================== GEMM2 (persistent): glu @ w_out[e], gate-scale scatter ====================
__global__ void __launch_bounds__(128) gemm2_mma(const __half* __restrict__ w2e) {
    extern __shared__ char smem[];
    int* s_dst = (int*)smem;
    const uint32_t su = smem_u32(smem);
    const uint32_t as_u = su + SM_AS, bs_u = su + SM_BS;

    const int tid = threadIdx.x;
    const int lane = tid & 31, wid = tid >> 5;
    const int wm = wid & 1, wn = wid >> 1;
    const int g = lane >> 2, tq = lane & 3;

    int woff[EDIM + 1];
#pragma unroll
    for (int k = 0; k <= EDIM; k++) woff[k] = g_w2off[k];
    const int tot = woff[EDIM];

    for (int w = blockIdx.x; w < tot; w += (int)gridDim.x) {
        int e = 0;
#pragma unroll
        for (int k = 1; k < EDIM; k++) e = (w >= woff[k]) ? k : e;
        const int local = w - woff[e];
        const int row0 = (local >> 3) * 128;
        const int n1 = (local & 7) << 7;
        const int cnt = g_freq[e];
        const int off = g_offsets[e];
        const int rlim = cnt - row0;

        __syncthreads();
        {
            int r = row0 + tid;
            s_dst[tid] = g_list[off + ((r < cnt) ? r : (cnt - 1))];
        }
        __syncthreads();

        const __half* w2 = w2e + (size_t)e * FDIM * HDIM;

        float acc[4][8][4];
#pragma unroll
        for (int i = 0; i < 4; i++)
#pragma unroll
            for (int f = 0; f < 8; f++)
#pragma unroll
                for (int q = 0; q < 4; q++) acc[i][f][q] = 0.f;

        const int NCH = FDIM / 32;  // 64
        g2_load(w2, off, row0, rlim, as_u, bs_u, tid, n1, 0, 0);
        g2_load(w2, off, row0, rlim, as_u, bs_u, tid, n1, 1, 1);
        CP_WAIT1();
        __syncthreads();

        for (int c = 0; c < NCH; c++) {
            const int st = c & 1;
            chunk_mma(as_u + st * A_STG_B, bs_u + st * B_STG_B, wm, wn, lane, acc);
            __syncthreads();
            if (c + 2 < NCH) g2_load(w2, off, row0, rlim, as_u, bs_u, tid, n1, c + 2, st);
            if (c + 1 < NCH) {
                if (c + 2 < NCH) CP_WAIT1(); else CP_WAIT0();
                __syncthreads();
            }
        }

        // epilogue: scale by gate, scatter rows to g_pairs[dst]
#pragma unroll
        for (int i = 0; i < 4; i++) {
            const int rbase = wm * 64 + i * 16 + g;
#pragma unroll
            for (int hr = 0; hr < 2; hr++) {
                const int r = rbase + hr * 8;
                if (r < rlim) {
                    const int dst = s_dst[r];
                    const float gt = g_gate[dst];
                    float* op = g_pairs + (size_t)dst * HDIM + n1 + wn * 64;
#pragma unroll
                    for (int f = 0; f < 8; f++) {
                        float2 o;
                        o.x = acc[i][f][hr * 2] * gt;
                        o.y = acc[i][f][hr * 2 + 1] * gt;
                        *(float2*)(op + f * 8 + 2 * tq) = o;
                    }
                }
            }
        }
    }
}

// ==================== combine (+ fused loss in last block) ====================
__global__ void combine_kernel(float* __restrict__ out, const float* __restrict__ bias,
                               int out_size) {
    int i = blockIdx.x * blockDim.x + threadIdx.x;
    if (i < TDIM * HDIM / 4) {
        int t = i >> 8;
        int c4 = i & 255;
        const float4* p4 = (const float4*)g_pairs;
        float4 a = p4[(size_t)(2 * t) * 256 + c4];
        float4 b = p4[(size_t)(2 * t) * 256 + 256 + c4];
        float4 bs = ((const float4*)bias)[c4];
        float4 o;
        o.x = a.x + b.x + bs.x; o.y = a.y + b.y + bs.y;
        o.z = a.z + b.z + bs.z; o.w = a.w + b.w + bs.w;
        ((float4*)out)[i] = o;
    }
    if (blockIdx.x == gridDim.x - 1 && threadIdx.x == 0) {
        float s = 0.f;
        for (int e = 0; e < EDIM; e++) s += g_psum[e] * (float)g_freq[e];
        float loss = (float)EDIM * s / ((float)TDIM * (float)(TDIM * KSEL))
                   + 0.1f * g_lsesq / (float)TDIM;
        if (out_size > TDIM * HDIM) out[TDIM * HDIM] = loss;
    }
}

// ==================== launch ====================
extern "C" void kernel_launch(void* const* d_in, const int* in_sizes, int n_in,
                              void* d_out, int out_size) {
    const float* x        = (const float*)d_in[0];
    const float* w_router = (const float*)d_in[1];
    const float* w_in     = (const float*)d_in[2];
    const float* w_out    = (const float*)d_in[3];
    const float* bias     = (const float*)d_in[4];
    float* out = (float*)d_out;

    // one-time handles (created on the non-captured correctness call; no device mem)
    static cudaStream_t s2 = nullptr;
    static cudaEvent_t evFork = nullptr, evW1 = nullptr, evW2 = nullptr;
    if (s2 == nullptr) {
        cudaStreamCreateWithFlags(&s2, cudaStreamNonBlocking);
        cudaEventCreateWithFlags(&evFork, cudaEventDisableTiming);
        cudaEventCreateWithFlags(&evW1, cudaEventDisableTiming);
        cudaEventCreateWithFlags(&evW2, cudaEventDisableTiming);
    }

    cudaFuncSetAttribute(gemm1_mma, cudaFuncAttributeMaxDynamicSharedMemorySize, GEMM_SMEM);
    cudaFuncSetAttribute(gemm2_mma, cudaFuncAttributeMaxDynamicSharedMemorySize, GEMM_SMEM);

    __half *w1h_p, *w2h_p;
    cudaGetSymbolAddress((void**)&w1h_p, g_w1h);
    cudaGetSymbolAddress((void**)&w2h_p, g_w2h);

    zero_kernel<<<1, 32>>>();

    // fork: weight fp16 conversions on side stream, overlapped with router/scatter/gemm1
    cudaEventRecord(evFork, 0);
    cudaStreamWaitEvent(s2, evFork, 0);
    {
        int n4w1 = EDIM * HDIM * 2 * FDIM / 4;
        convh_kernel<<<(n4w1 + 255) / 256, 256, 0, s2>>>((const float4*)w_in, (uint2*)w1h_p, n4w1);
        cudaEventRecord(evW1, s2);
        int n4w2 = EDIM * FDIM * HDIM / 4;
        convh_kernel<<<(n4w2 + 255) / 256, 256, 0, s2>>>((const float4*)w_out, (uint2*)w2h_p, n4w2);
        cudaEventRecord(evW2, s2);
    }

    // main stream: router (+x fp16), dispatch build
    router_kernel<<<TDIM / 8, 256>>>(x, w_router);
    scan_kernel<<<1, 32>>>();
    scatter_kernel<<<NROWS / 256, 256>>>();

    cudaStreamWaitEvent(0, evW1, 0);   // join: gemm1 needs w1h
    gemm1_mma<<<GEMM_GRID, 128, GEMM_SMEM>>>(w1h_p);

    cudaStreamWaitEvent(0, evW2, 0);   // join: gemm2 needs w2h
    gemm2_mma<<<GEMM_GRID, 128, GEMM_SMEM>>>(w2h_p);

    combine_kernel<<<(TDIM * HDIM / 4 + 255) / 256, 256>>>(out, bias, out_size);
}